// round 5
// baseline (speedup 1.0000x reference)
#include <cuda_runtime.h>
#include <math.h>

#define BB 1024
#define DD 1024
#define NN 128
#define PT 28
#define SG 4   // steps per table block (PT/7)

// scratch (device globals — no allocation allowed)
__device__ __align__(16) float g_hs[PT * DD];     // silu(s*w1+b1) per step value s
__device__ __align__(16) float g_E[PT * DD];      // t_embed table per step value
__device__ __align__(16) float g_L[PT * NN];      // clean logits table
__device__ __align__(16) float g_S[PT * NN];      // noise std table
__device__ __align__(16) float g_gates[BB * NN];  // per-row gates
__device__ int g_is64;                            // timestep dtype flag

__device__ __forceinline__ int get_ts(const int* ts32, int b) {
    return g_is64 ? ts32[2 * b] : ts32[b];
}

// K1: hs[s][d] = silu(s * w1[d] + b1[d]); last block also sniffs timestep dtype.
// int64 LE array of small nonneg values => every odd int32 word is 0.
__global__ void k_hs(const float* __restrict__ w1, const float* __restrict__ b1,
                     const int* __restrict__ ts32) {
    if (blockIdx.x == gridDim.x - 1) {
        int t = threadIdx.x;
        int any = 0;
#pragma unroll
        for (int r = 0; r < 4; r++) {
            int idx = t + r * 256;  // 0..1023
            any |= (ts32[2 * idx + 1] != 0);
        }
        any = __syncthreads_or(any);
        if (t == 0) g_is64 = !any;
        return;
    }
    int i = blockIdx.x * blockDim.x + threadIdx.x;
    if (i < PT * DD) {
        int s = i / DD, d = i - s * DD;
        float x = (float)s * w1[d] + b1[d];
        g_hs[i] = x / (1.0f + expf(-x));
    }
}

// K2: E[s][j] = dot(hs[s], w2[j,:]) + b2[j].  One block per j, 28 steps at once
// so w2 (4MB) is streamed exactly once.
__global__ __launch_bounds__(256) void k_E(const float* __restrict__ w2,
                                           const float* __restrict__ b2) {
    int j = blockIdx.x, t = threadIdx.x;
    float acc[PT];
#pragma unroll
    for (int s = 0; s < PT; s++) acc[s] = 0.f;
#pragma unroll
    for (int dd = 0; dd < 4; dd++) {
        int d = t + dd * 256;
        float w = __ldg(&w2[(size_t)j * DD + d]);
#pragma unroll
        for (int s = 0; s < PT; s++) acc[s] = fmaf(__ldg(&g_hs[s * DD + d]), w, acc[s]);
    }
#pragma unroll
    for (int s = 0; s < PT; s++)
        for (int o = 16; o > 0; o >>= 1)
            acc[s] += __shfl_xor_sync(0xffffffffu, acc[s], o);
    __shared__ float red[PT][8];
    int wid = t >> 5, lane = t & 31;
    if (lane == 0) {
#pragma unroll
        for (int s = 0; s < PT; s++) red[s][wid] = acc[s];
    }
    __syncthreads();
    if (t < PT) {
        float v = 0.f;
#pragma unroll
        for (int w8 = 0; w8 < 8; w8++) v += red[t][w8];
        g_E[t * DD + j] = v + b2[j];
    }
}

// K3: L[s][n] = dot(E[s], gate_w[n,:D]) + step*gate_w[n,D] + gate_b[n]
//     S[s][n] = softplus(dot(E[s], w_noise[:,n])) + 0.01
// Split over 7 step-groups of 4 for occupancy / short dep chains.
__global__ __launch_bounds__(256) void k_tables(const float* __restrict__ gate_w,
                                                const float* __restrict__ gate_b,
                                                const float* __restrict__ w_noise,
                                                const int* __restrict__ ts32) {
    int n = blockIdx.x, t = threadIdx.x;
    int s0 = blockIdx.y * SG;
    float al[SG], an[SG];
#pragma unroll
    for (int s = 0; s < SG; s++) { al[s] = 0.f; an[s] = 0.f; }
#pragma unroll
    for (int dd = 0; dd < 4; dd++) {
        int d = t + dd * 256;
        float gw = __ldg(&gate_w[(size_t)n * (DD + 1) + d]);
        float wn = __ldg(&w_noise[(size_t)d * NN + n]);
#pragma unroll
        for (int s = 0; s < SG; s++) {
            float e = __ldg(&g_E[(s0 + s) * DD + d]);
            al[s] = fmaf(e, gw, al[s]);
            an[s] = fmaf(e, wn, an[s]);
        }
    }
#pragma unroll
    for (int s = 0; s < SG; s++)
        for (int o = 16; o > 0; o >>= 1) {
            al[s] += __shfl_xor_sync(0xffffffffu, al[s], o);
            an[s] += __shfl_xor_sync(0xffffffffu, an[s], o);
        }
    __shared__ float rl[SG][8], rn[SG][8];
    int wid = t >> 5, lane = t & 31;
    if (lane == 0) {
#pragma unroll
        for (int s = 0; s < SG; s++) { rl[s][wid] = al[s]; rn[s][wid] = an[s]; }
    }
    __syncthreads();
    if (t < SG) {
        float vl = 0.f, vn = 0.f;
#pragma unroll
        for (int w8 = 0; w8 < 8; w8++) { vl += rl[t][w8]; vn += rn[t][w8]; }
        int s = s0 + t;
        float stepf = (float)get_ts(ts32, 0);
        g_L[s * NN + n] = vl + stepf * gate_w[(size_t)n * (DD + 1) + DD] + gate_b[n];
        float x = vn;
        float sp = fmaxf(x, 0.f) + log1pf(expf(-fabsf(x)));
        g_S[s * NN + n] = sp + 0.01f;
    }
}

// K4: warp-per-row noisy top-32 softmax gating + t_embed rows.
// 4 logits per lane; rank+max via 32-step shuffle broadcast; no smem, no BARs.
__global__ __launch_bounds__(128) void k_gate(const float* __restrict__ noise,
                                              const int* __restrict__ ts32,
                                              float* __restrict__ out_tembed) {
    const unsigned FULL = 0xffffffffu;
    int warp = threadIdx.x >> 5, lane = threadIdx.x & 31;
    int b = blockIdx.x * 4 + warp;
    int s = get_ts(ts32, b);

    float4 L4 = *(const float4*)&g_L[s * NN + lane * 4];
    float4 S4 = *(const float4*)&g_S[s * NN + lane * 4];
    float4 Z4 = __ldg(((const float4*)(noise + (size_t)b * NN)) + lane);

    float l[4];
    l[0] = fmaf(Z4.x, S4.x, L4.x);
    l[1] = fmaf(Z4.y, S4.y, L4.y);
    l[2] = fmaf(Z4.z, S4.z, L4.z);
    l[3] = fmaf(Z4.w, S4.w, L4.w);

    int rank[4] = {0, 0, 0, 0};
    float gmx = -INFINITY;
    int nbase = lane * 4;
#pragma unroll 4
    for (int i = 0; i < 32; i++) {
        float o0 = __shfl_sync(FULL, l[0], i);
        float o1 = __shfl_sync(FULL, l[1], i);
        float o2 = __shfl_sync(FULL, l[2], i);
        float o3 = __shfl_sync(FULL, l[3], i);
        gmx = fmaxf(gmx, fmaxf(fmaxf(o0, o1), fmaxf(o2, o3)));
        int mb = i * 4;
#pragma unroll
        for (int k = 0; k < 4; k++) {
            int n = nbase + k;
            float lk = l[k];
            rank[k] += (o0 > lk) || (o0 == lk && mb + 0 < n);
            rank[k] += (o1 > lk) || (o1 == lk && mb + 1 < n);
            rank[k] += (o2 > lk) || (o2 == lk && mb + 2 < n);
            rank[k] += (o3 > lk) || (o3 == lk && mb + 3 < n);
        }
    }

    float e[4];
#pragma unroll
    for (int k = 0; k < 4; k++)
        e[k] = (rank[k] < 32) ? expf(l[k] - gmx) : 0.f;  // top-(k-1)=32 selected

    float esum = e[0] + e[1] + e[2] + e[3];
#pragma unroll
    for (int o = 16; o > 0; o >>= 1) esum += __shfl_xor_sync(FULL, esum, o);
    float inv = 1.f / esum;

    float4 gout = make_float4(e[0] * inv, e[1] * inv, e[2] * inv, e[3] * inv);
    __stcs(((float4*)&g_gates[(size_t)b * NN]) + lane, gout);

    // t_embed[b] = E[timestep[b]] — streaming vectorized copy (E row is L2-hot)
    const float4* er = (const float4*)&g_E[s * DD];
    float4* tr = (float4*)(out_tembed + (size_t)b * DD);
#pragma unroll
    for (int p = 0; p < 8; p++) __stcs(&tr[lane + p * 32], er[lane + p * 32]);
}

// K5: out[b,n,:] = prompts[step][n,:] * gates[b,n].  16 b-rows per block so the
// prompt row (4KB) is read once per 64KB of streaming stores.
__global__ __launch_bounds__(256) void k_out(const float* __restrict__ pe,
                                             const int* __restrict__ ts32,
                                             float* __restrict__ out) {
    int n = blockIdx.x;         // 0..127
    int b0 = blockIdx.y * 16;   // 16 batch rows per block
    int t = threadIdx.x;        // 256 -> one float4 each
    int step = get_ts(ts32, 0);
    const float4* prow = (const float4*)(pe + ((size_t)step * NN + n) * DD);
    float4 v = __ldg(&prow[t]);
    float4* o4 = (float4*)out;
#pragma unroll
    for (int bb = 0; bb < 16; bb++) {
        int b = b0 + bb;
        float g = __ldg(&g_gates[(size_t)b * NN + n]);
        float4 o = make_float4(v.x * g, v.y * g, v.z * g, v.w * g);
        __stcs(&o4[((size_t)b * NN + n) * (DD / 4) + t], o);
    }
}

extern "C" void kernel_launch(void* const* d_in, const int* in_sizes, int n_in,
                              void* d_out, int out_size) {
    const float* pe      = (const float*)d_in[0];  // [28,128,1024]
    const float* w1      = (const float*)d_in[1];  // [1024]
    const float* b1      = (const float*)d_in[2];  // [1024]
    const float* w2      = (const float*)d_in[3];  // [1024,1024]
    const float* b2      = (const float*)d_in[4];  // [1024]
    const float* gate_w  = (const float*)d_in[5];  // [128,1025]
    const float* gate_b  = (const float*)d_in[6];  // [128]
    const float* w_noise = (const float*)d_in[7];  // [1024,128]
    const float* noise   = (const float*)d_in[8];  // [1024,128]
    const int*   ts32    = (const int*)d_in[9];    // [1024] int32 or int64 (detected)

    float* out        = (float*)d_out;                         // [B,N,D]
    float* out_tembed = (float*)d_out + (size_t)BB * NN * DD;  // [B,D]

    k_hs<<<(PT * DD + 255) / 256 + 1, 256>>>(w1, b1, ts32);
    k_E<<<DD, 256>>>(w2, b2);
    k_tables<<<dim3(NN, PT / SG), 256>>>(gate_w, gate_b, w_noise, ts32);
    k_gate<<<BB / 4, 128>>>(noise, ts32, out_tembed);
    k_out<<<dim3(NN, BB / 16), 256>>>(pe, ts32, out);
}

// round 6
// speedup vs baseline: 1.0408x; 1.0408x over previous
#include <cuda_runtime.h>
#include <math.h>

#define BB 1024
#define DD 1024
#define NN 128
#define PT 28
#define SG 4    // steps per k_tables block
#define JT 4    // j's per k_E block
#define SGE 7   // steps per k_E block

// scratch (device globals — no allocation allowed)
__device__ __align__(16) float g_hs[PT * DD];     // silu(s*w1+b1) per step value s
__device__ __align__(16) float g_E[PT * DD];      // t_embed table per step value
__device__ __align__(16) float g_L[PT * NN];      // clean logits table
__device__ __align__(16) float g_S[PT * NN];      // noise std table
__device__ __align__(16) float g_gates[BB * NN];  // per-row gates
__device__ int g_is64;                            // timestep dtype flag

__device__ __forceinline__ int get_ts(const int* ts32, int b) {
    return g_is64 ? ts32[2 * b] : ts32[b];
}

// K1: hs[s][d] = silu(s * w1[d] + b1[d]); last block sniffs timestep dtype.
// int64 LE array of small nonneg values => every odd int32 word is 0.
__global__ void k_hs(const float* __restrict__ w1, const float* __restrict__ b1,
                     const int* __restrict__ ts32) {
    if (blockIdx.x == gridDim.x - 1) {
        int t = threadIdx.x;
        int any = 0;
#pragma unroll
        for (int r = 0; r < 4; r++) {
            int idx = t + r * 256;  // 0..1023
            any |= (ts32[2 * idx + 1] != 0);
        }
        any = __syncthreads_or(any);
        if (t == 0) g_is64 = !any;
        return;
    }
    int i = blockIdx.x * blockDim.x + threadIdx.x;
    if (i < PT * DD) {
        int s = i / DD, d = i - s * DD;
        float x = (float)s * w1[d] + b1[d];
        g_hs[i] = x / (1.0f + expf(-x));
    }
}

// K2: E[s][j] = dot(hs[s], w2[j,:]) + b2[j].
// Block = (4 j's) x (7 s's); thread covers d-range [t*4, t*4+4) via float4.
// hs L2 traffic: 28KB/block * 1024 blocks = 28MB (was 112MB); 4x MLP on loads.
__global__ __launch_bounds__(256) void k_E(const float* __restrict__ w2,
                                           const float* __restrict__ b2) {
    int jb = blockIdx.x, sb = blockIdx.y, t = threadIdx.x;
    int j0 = jb * JT, s0 = sb * SGE;

    float4 w[JT];
#pragma unroll
    for (int jj = 0; jj < JT; jj++)
        w[jj] = __ldg(((const float4*)(w2 + (size_t)(j0 + jj) * DD)) + t);

    float acc[SGE][JT];
#pragma unroll
    for (int ss = 0; ss < SGE; ss++)
#pragma unroll
        for (int jj = 0; jj < JT; jj++) acc[ss][jj] = 0.f;

#pragma unroll
    for (int ss = 0; ss < SGE; ss++) {
        float4 h = __ldg(((const float4*)(g_hs + (s0 + ss) * DD)) + t);
#pragma unroll
        for (int jj = 0; jj < JT; jj++) {
            float a = fmaf(h.x, w[jj].x, h.y * w[jj].y);
            float c = fmaf(h.z, w[jj].z, h.w * w[jj].w);
            acc[ss][jj] += a + c;
        }
    }

    // warp reduce all 28 accumulators
#pragma unroll
    for (int ss = 0; ss < SGE; ss++)
#pragma unroll
        for (int jj = 0; jj < JT; jj++)
#pragma unroll
            for (int o = 16; o > 0; o >>= 1)
                acc[ss][jj] += __shfl_xor_sync(0xffffffffu, acc[ss][jj], o);

    __shared__ float red[SGE * JT][8];
    int wid = t >> 5, lane = t & 31;
    if (lane == 0) {
#pragma unroll
        for (int ss = 0; ss < SGE; ss++)
#pragma unroll
            for (int jj = 0; jj < JT; jj++) red[ss * JT + jj][wid] = acc[ss][jj];
    }
    __syncthreads();
    if (t < SGE * JT) {
        float v = 0.f;
#pragma unroll
        for (int w8 = 0; w8 < 8; w8++) v += red[t][w8];
        int ss = t / JT, jj = t - ss * JT;
        g_E[(s0 + ss) * DD + j0 + jj] = v + b2[j0 + jj];
    }
}

// K3: L[s][n] = dot(E[s], gate_w[n,:D]) + step*gate_w[n,D] + gate_b[n]
//     S[s][n] = softplus(dot(E[s], w_noise[:,n])) + 0.01
__global__ __launch_bounds__(256) void k_tables(const float* __restrict__ gate_w,
                                                const float* __restrict__ gate_b,
                                                const float* __restrict__ w_noise,
                                                const int* __restrict__ ts32) {
    int n = blockIdx.x, t = threadIdx.x;
    int s0 = blockIdx.y * SG;
    float al[SG], an[SG];
#pragma unroll
    for (int s = 0; s < SG; s++) { al[s] = 0.f; an[s] = 0.f; }
#pragma unroll
    for (int dd = 0; dd < 4; dd++) {
        int d = t + dd * 256;
        float gw = __ldg(&gate_w[(size_t)n * (DD + 1) + d]);
        float wn = __ldg(&w_noise[(size_t)d * NN + n]);
#pragma unroll
        for (int s = 0; s < SG; s++) {
            float e = __ldg(&g_E[(s0 + s) * DD + d]);
            al[s] = fmaf(e, gw, al[s]);
            an[s] = fmaf(e, wn, an[s]);
        }
    }
#pragma unroll
    for (int s = 0; s < SG; s++)
#pragma unroll
        for (int o = 16; o > 0; o >>= 1) {
            al[s] += __shfl_xor_sync(0xffffffffu, al[s], o);
            an[s] += __shfl_xor_sync(0xffffffffu, an[s], o);
        }
    __shared__ float rl[SG][8], rn[SG][8];
    int wid = t >> 5, lane = t & 31;
    if (lane == 0) {
#pragma unroll
        for (int s = 0; s < SG; s++) { rl[s][wid] = al[s]; rn[s][wid] = an[s]; }
    }
    __syncthreads();
    if (t < SG) {
        float vl = 0.f, vn = 0.f;
#pragma unroll
        for (int w8 = 0; w8 < 8; w8++) { vl += rl[t][w8]; vn += rn[t][w8]; }
        int s = s0 + t;
        float stepf = (float)get_ts(ts32, 0);
        g_L[s * NN + n] = vl + stepf * gate_w[(size_t)n * (DD + 1) + DD] + gate_b[n];
        float x = vn;
        float sp = fmaxf(x, 0.f) + log1pf(expf(-fabsf(x)));
        g_S[s * NN + n] = sp + 0.01f;
    }
}

// K4: one block (4 warps) per row. Each warp holds the full 128 logits
// (4/lane) and computes partial ranks for its 8 of 32 broadcast rounds;
// partials combined via smem. 4096 warps total (~28/SM).
__global__ __launch_bounds__(128) void k_gate(const float* __restrict__ noise,
                                              const int* __restrict__ ts32,
                                              float* __restrict__ out_tembed) {
    const unsigned FULL = 0xffffffffu;
    int warp = threadIdx.x >> 5, lane = threadIdx.x & 31;
    int b = blockIdx.x;
    int s = get_ts(ts32, b);

    // t_embed[b] = E[s] — issue stores early, overlap with rank math.
    {
        const float4* er = (const float4*)&g_E[s * DD];
        float4* tr = (float4*)(out_tembed + (size_t)b * DD);
        int idx = threadIdx.x;  // 0..127; 256 float4 total
        __stcs(&tr[idx], er[idx]);
        __stcs(&tr[idx + 128], er[idx + 128]);
    }

    float4 L4 = *(const float4*)&g_L[s * NN + lane * 4];
    float4 S4 = *(const float4*)&g_S[s * NN + lane * 4];
    float4 Z4 = __ldg(((const float4*)(noise + (size_t)b * NN)) + lane);

    float l[4];
    l[0] = fmaf(Z4.x, S4.x, L4.x);
    l[1] = fmaf(Z4.y, S4.y, L4.y);
    l[2] = fmaf(Z4.z, S4.z, L4.z);
    l[3] = fmaf(Z4.w, S4.w, L4.w);

    int rank[4] = {0, 0, 0, 0};
    float mx = -INFINITY;
    int nbase = lane * 4;
#pragma unroll
    for (int ii = 0; ii < 8; ii++) {
        int i = warp * 8 + ii;  // broadcast lane (global values 4i..4i+3)
        float o0 = __shfl_sync(FULL, l[0], i);
        float o1 = __shfl_sync(FULL, l[1], i);
        float o2 = __shfl_sync(FULL, l[2], i);
        float o3 = __shfl_sync(FULL, l[3], i);
        mx = fmaxf(mx, fmaxf(fmaxf(o0, o1), fmaxf(o2, o3)));
        int mb = i * 4;
#pragma unroll
        for (int k = 0; k < 4; k++) {
            int n = nbase + k;
            float lk = l[k];
            rank[k] += (o0 > lk) || (o0 == lk && mb + 0 < n);
            rank[k] += (o1 > lk) || (o1 == lk && mb + 1 < n);
            rank[k] += (o2 > lk) || (o2 == lk && mb + 2 < n);
            rank[k] += (o3 > lk) || (o3 == lk && mb + 3 < n);
        }
    }

    __shared__ int prank[4][NN];
    __shared__ float pmax[4];
    *(int4*)&prank[warp][lane * 4] = make_int4(rank[0], rank[1], rank[2], rank[3]);
    if (lane == 0) pmax[warp] = mx;  // mx is lane-uniform (built from broadcasts)
    __syncthreads();

    if (warp == 0) {
        float gmx = fmaxf(fmaxf(pmax[0], pmax[1]), fmaxf(pmax[2], pmax[3]));
        int4 r0 = *(const int4*)&prank[0][lane * 4];
        int4 r1 = *(const int4*)&prank[1][lane * 4];
        int4 r2 = *(const int4*)&prank[2][lane * 4];
        int4 r3 = *(const int4*)&prank[3][lane * 4];
        int rt[4];
        rt[0] = r0.x + r1.x + r2.x + r3.x;
        rt[1] = r0.y + r1.y + r2.y + r3.y;
        rt[2] = r0.z + r1.z + r2.z + r3.z;
        rt[3] = r0.w + r1.w + r2.w + r3.w;

        float e[4];
#pragma unroll
        for (int k = 0; k < 4; k++)
            e[k] = (rt[k] < 32) ? expf(l[k] - gmx) : 0.f;  // top-(k-1)=32

        float esum = e[0] + e[1] + e[2] + e[3];
#pragma unroll
        for (int o = 16; o > 0; o >>= 1) esum += __shfl_xor_sync(FULL, esum, o);
        float inv = 1.f / esum;

        float4 gout = make_float4(e[0] * inv, e[1] * inv, e[2] * inv, e[3] * inv);
        __stcs(((float4*)&g_gates[(size_t)b * NN]) + lane, gout);
    }
}

// K5: out[b,n,:] = prompts[step][n,:] * gates[b,n].  16 b-rows per block so the
// prompt row (4KB) is read once per 64KB of streaming stores.
__global__ __launch_bounds__(256) void k_out(const float* __restrict__ pe,
                                             const int* __restrict__ ts32,
                                             float* __restrict__ out) {
    int n = blockIdx.x;         // 0..127
    int b0 = blockIdx.y * 16;   // 16 batch rows per block
    int t = threadIdx.x;        // 256 -> one float4 each
    int step = get_ts(ts32, 0);
    const float4* prow = (const float4*)(pe + ((size_t)step * NN + n) * DD);
    float4 v = __ldg(&prow[t]);
    float4* o4 = (float4*)out;
#pragma unroll
    for (int bb = 0; bb < 16; bb++) {
        int b = b0 + bb;
        float g = __ldg(&g_gates[(size_t)b * NN + n]);
        float4 o = make_float4(v.x * g, v.y * g, v.z * g, v.w * g);
        __stcs(&o4[((size_t)b * NN + n) * (DD / 4) + t], o);
    }
}

extern "C" void kernel_launch(void* const* d_in, const int* in_sizes, int n_in,
                              void* d_out, int out_size) {
    const float* pe      = (const float*)d_in[0];  // [28,128,1024]
    const float* w1      = (const float*)d_in[1];  // [1024]
    const float* b1      = (const float*)d_in[2];  // [1024]
    const float* w2      = (const float*)d_in[3];  // [1024,1024]
    const float* b2      = (const float*)d_in[4];  // [1024]
    const float* gate_w  = (const float*)d_in[5];  // [128,1025]
    const float* gate_b  = (const float*)d_in[6];  // [128]
    const float* w_noise = (const float*)d_in[7];  // [1024,128]
    const float* noise   = (const float*)d_in[8];  // [1024,128]
    const int*   ts32    = (const int*)d_in[9];    // [1024] int32 or int64 (detected)

    float* out        = (float*)d_out;                         // [B,N,D]
    float* out_tembed = (float*)d_out + (size_t)BB * NN * DD;  // [B,D]

    k_hs<<<(PT * DD + 255) / 256 + 1, 256>>>(w1, b1, ts32);
    k_E<<<dim3(DD / JT, PT / SGE), 256>>>(w2, b2);
    k_tables<<<dim3(NN, PT / SG), 256>>>(gate_w, gate_b, w_noise, ts32);
    k_gate<<<BB, 128>>>(noise, ts32, out_tembed);
    k_out<<<dim3(NN, BB / 16), 256>>>(pe, ts32, out);
}